// round 10
// baseline (speedup 1.0000x reference)
#include <cuda_runtime.h>
#include <math.h>
#include <limits.h>

// Problem constants (fixed by the reference setup_inputs)
#define BB    4
#define NN    8192
#define MM    8192
#define TPB   256
#define SPLIT 8
#define CH    (MM / SPLIT)            // 1024 context points per chunk
#define BPB   (NN / TPB)              // 32 query-blocks per batch

// Output layout: [unit BB*3*NN][cen BB*3*NN][pos BB*NN]
#define OFF_U 0
#define OFF_C (BB * 3 * NN)
#define OFF_P (2 * BB * 3 * NN)

// Scratch (allocation-free: __device__ globals)
__device__ float g_pd[3 * SPLIT * BB * NN];
__device__ int   g_pi[3 * SPLIT * BB * NN];
__device__ unsigned char g_mask[BB * NN];
__device__ int g_first[BB];

#define PD(k, s, q) g_pd[(((k) * SPLIT + (s)) * (BB * NN)) + (q)]
#define PI(k, s, q) g_pi[(((k) * SPLIT + (s)) * (BB * NN)) + (q)]

// ---- packed f32x2 helpers (Blackwell sm_100+): mul/add/fma only ----
typedef unsigned long long u64;

__device__ __forceinline__ u64 f2pk(float lo, float hi) {
    u64 r;
    asm("mov.b64 %0, {%1, %2};" : "=l"(r)
        : "r"(__float_as_uint(lo)), "r"(__float_as_uint(hi)));
    return r;
}
__device__ __forceinline__ void f2un(u64 v, float& lo, float& hi) {
    unsigned a, b;
    asm("mov.b64 {%0, %1}, %2;" : "=r"(a), "=r"(b) : "l"(v));
    lo = __uint_as_float(a); hi = __uint_as_float(b);
}
__device__ __forceinline__ u64 mul2(u64 a, u64 b) {
    u64 r; asm("mul.rn.f32x2 %0, %1, %2;" : "=l"(r) : "l"(a), "l"(b)); return r;
}
__device__ __forceinline__ u64 add2(u64 a, u64 b) {
    u64 r; asm("add.rn.f32x2 %0, %1, %2;" : "=l"(r) : "l"(a), "l"(b)); return r;
}
__device__ __forceinline__ u64 fma2(u64 a, u64 b, u64 c) {
    u64 r; asm("fma.rn.f32x2 %0, %1, %2, %3;" : "=l"(r) : "l"(a), "l"(b), "l"(c)); return r;
}

// Sign-bit any-negative test: OR-fold the four 32-bit words of two packed
// differences, check the sign bit. (a-b)<0 iff a<b; a==b gives +0 (not taken).
__device__ __forceinline__ bool any_neg4(u64 s0, u64 s1) {
    unsigned a, b, c, d;
    asm("mov.b64 {%0, %1}, %2;" : "=r"(a), "=r"(b) : "l"(s0));
    asm("mov.b64 {%0, %1}, %2;" : "=r"(c), "=r"(d) : "l"(s1));
    return (int)(a | b | c | d) < 0;
}

// Branchless stable top-3 insert (FSETP+SEL). Strict '<' keeps the
// earlier-inserted entry on exact ties => apply in ascending-j order,
// matching lax.top_k.
#define INSB(d, jj) {                                                        \
    bool lt2 = (d) < d2, lt1 = (d) < d1, lt0 = (d) < d0;                     \
    float nd2 = lt1 ? d1 : (d);  int ni2 = lt1 ? i1 : (jj);                  \
    float nd1 = lt0 ? d0 : (d);  int ni1 = lt0 ? i0 : (jj);                  \
    d2 = lt2 ? nd2 : d2;  i2 = lt2 ? ni2 : i2;                               \
    d1 = lt1 ? nd1 : d1;  i1 = lt1 ? ni1 : i1;                               \
    d0 = lt0 ? (d) : d0;  i0 = lt0 ? (jj) : i0;                              \
}

__global__ void __launch_bounds__(TPB)
surf_scan_kernel(const float* __restrict__ center,
                 const float* __restrict__ context)
{
    // Interleaved packed layout: per point-pair p (points 2p, 2p+1),
    // sD[4p..4p+3] = { (x0,x1), (y0,y1), (z0,z1), (w0,w1) }  (32 bytes).
    __shared__ __align__(16) u64 sD[(CH / 2) * 4];   // 16 KB

    // One-time scratch init for this replay (merge runs after scan completes)
    if (blockIdx.x < BB && threadIdx.x == 0) g_first[blockIdx.x] = INT_MAX;

    // blockIdx.x = ((b * BPB) + qb) * SPLIT + s
    const int s  = blockIdx.x % SPLIT;
    const int r  = blockIdx.x / SPLIT;
    const int qb = r % BPB;
    const int b  = r / BPB;
    const int j0 = s * CH;

    // Load phase: pack into interleaved f32x2 words (8-byte granular writes)
    const float* ctx = context + (size_t)b * 3 * MM;
    for (int j = threadIdx.x; j < CH; j += TPB) {
        float x = ctx[j0 + j];
        float y = ctx[MM + j0 + j];
        float z = ctx[2 * MM + j0 + j];
        float w = x * x + y * y + z * z;
        const int p = j >> 1, l = j & 1;
        float* f = (float*)&sD[4 * p];
        f[l]     = x;   // (x0,x1)
        f[2 + l] = y;   // (y0,y1)
        f[4 + l] = z;   // (z0,z1)
        f[6 + l] = w;   // (w0,w1)
    }
    __syncthreads();

    // This thread's query point
    const int n = qb * TPB + threadIdx.x;
    const float* cenp = center + (size_t)b * 3 * NN;
    const float qx = cenp[n];
    const float qy = cenp[NN + n];
    const float qz = cenp[2 * NN + n];
    const float cn = qx * qx + qy * qy + qz * qz;

    const u64 QX2  = f2pk(qx, qx);
    const u64 QY2  = f2pk(qy, qy);
    const u64 QZ2  = f2pk(qz, qz);
    const u64 CN2  = f2pk(cn, cn);
    const u64 NEG2 = f2pk(-2.0f, -2.0f);

    float d0 = INFINITY, d1 = INFINITY, d2 = INFINITY;
    int   i0 = 0, i1 = 0, i2 = 0;
    u64 ND2P = f2pk(-INFINITY, -INFINITY);   // packed (-d2, -d2)

    const ulonglong2* sV = (const ulonglong2*)sD;

    #pragma unroll 4
    for (int p = 0; p < CH / 2; p += 2) {     // 4 points per iteration
        ulonglong2 a0 = sV[2 * p];            // {x01, y01}
        ulonglong2 a1 = sV[2 * p + 1];        // {z01, w01}
        ulonglong2 a2 = sV[2 * p + 2];        // {x23, y23}
        ulonglong2 a3 = sV[2 * p + 3];        // {z23, w23}

        // d = (cn + |p|^2) - 2*dot — identical op sequence to prior rounds
        u64 t0 = mul2(QX2, a0.x);
        t0 = fma2(QY2, a0.y, t0);
        t0 = fma2(QZ2, a1.x, t0);
        u64 dp0 = fma2(NEG2, t0, add2(CN2, a1.y));

        u64 t1 = mul2(QX2, a2.x);
        t1 = fma2(QY2, a2.y, t1);
        t1 = fma2(QZ2, a3.x, t1);
        u64 dp1 = fma2(NEG2, t1, add2(CN2, a3.y));

        // Filter on the fma pipe: d - d2 packed; branch if any sign bit set.
        u64 s0 = add2(dp0, ND2P);
        u64 s1 = add2(dp1, ND2P);

        if (any_neg4(s0, s1)) {               // rare (~5% of groups)
            float da, db, dc, dd;
            f2un(dp0, da, db);
            f2un(dp1, dc, dd);
            const int jj = j0 + 2 * p;
            bool pa = da < d2, pb = db < d2, pc = dc < d2, pd = dd < d2;
            int cnt = (int)pa + (int)pb + (int)pc + (int)pd;
            if (cnt == 1) {
                // exactly one candidate: order-independent single insert
                float ds = pa ? da : (pb ? db : (pc ? dc : dd));
                int   js = pa ? jj : (pb ? jj + 1 : (pc ? jj + 2 : jj + 3));
                INSB(ds, js);
            } else if (cnt > 1) {
                // ascending-j sequential inserts: exact tie semantics
                INSB(da, jj);
                INSB(db, jj + 1);
                INSB(dc, jj + 2);
                INSB(dd, jj + 3);
            }
            // (cnt==0 possible only via the -0 false positive: d == d2)
            ND2P = f2pk(-d2, -d2);
        }
    }

    const int q = b * NN + n;
    PD(0, s, q) = d0;  PI(0, s, q) = i0;
    PD(1, s, q) = d1;  PI(1, s, q) = i1;
    PD(2, s, q) = d2;  PI(2, s, q) = i2;
}

// Merge SPLIT partial triples per query, epilogue, mask, first-good-row.
__global__ void __launch_bounds__(256)
surf_merge_kernel(const float* __restrict__ context,
                  float* __restrict__ out)
{
    const int q = blockIdx.x * blockDim.x + threadIdx.x;
    if (q >= BB * NN) return;
    const int b = q / NN;
    const int n = q % NN;

    float d0 = INFINITY, d1 = INFINITY, d2 = INFINITY;
    int   i0 = 0, i1 = 0, i2 = 0;

    // Ascending split order + rank order -> exact global-scan tie semantics.
    #pragma unroll
    for (int s = 0; s < SPLIT; s++) {
        #pragma unroll
        for (int k = 0; k < 3; k++) {
            float d  = PD(k, s, q);
            int   jj = PI(k, s, q);
            INSB(d, jj);
        }
    }

    const float* ctx = context + (size_t)b * 3 * MM;
    float g0x = ctx[i0], g0y = ctx[MM + i0], g0z = ctx[2 * MM + i0];
    float g1x = ctx[i1], g1y = ctx[MM + i1], g1z = ctx[2 * MM + i1];
    float g2x = ctx[i2], g2y = ctx[MM + i2], g2z = ctx[2 * MM + i2];

    float e1x = g1x - g0x, e1y = g1y - g0y, e1z = g1z - g0z;
    float e2x = g2x - g0x, e2y = g2y - g0y, e2z = g2z - g0z;

    float nx = e1y * e2z - e1z * e2y;
    float ny = e1z * e2x - e1x * e2z;
    float nz = e1x * e2y - e1y * e2x;

    float nrm = sqrtf(nx * nx + ny * ny + nz * nz);
    float ux = nx / nrm;
    float uy = ny / nrm;
    float uz = nz / nrm;

    float sg = (ux > 0.0f) ? 1.0f : -1.0f;   // NaN compares false -> -1
    ux *= sg; uy *= sg; uz *= sg;

    float cx = (g0x + g1x + g2x) / 3.0f;
    float cy = (g0y + g1y + g2y) / 3.0f;
    float cz = (g0z + g1z + g2z) / 3.0f;

    float pos = (ux * cx + uy * cy + uz * cz) / sqrtf(3.0f);

    bool bad = (ux != ux) || (uy != uy) || (uz != uz);
    g_mask[q] = bad ? 1 : 0;

    // first non-NaN row per batch: warp-reduce then one atomic per warp.
    // Block covers consecutive q within ONE batch (NN % 256 == 0).
    int v = bad ? INT_MAX : n;
    int wmin = __reduce_min_sync(0xffffffffu, v);
    if ((threadIdx.x & 31) == 0 && wmin != INT_MAX)
        atomicMin(&g_first[b], wmin);

    const size_t base = (size_t)b * 3 * NN + n;
    out[OFF_U + base]          = ux;
    out[OFF_U + base + NN]     = uy;
    out[OFF_U + base + 2 * NN] = uz;
    out[OFF_C + base]          = cx;
    out[OFF_C + base + NN]     = cy;
    out[OFF_C + base + 2 * NN] = cz;
    out[OFF_P + (size_t)b * NN + n] = pos;
}

// Rewrite masked rows with the first non-NaN row's values
__global__ void surf_fix_kernel(float* __restrict__ out)
{
    const int idx = blockIdx.x * blockDim.x + threadIdx.x;
    if (idx >= BB * NN) return;
    if (!g_mask[idx]) return;

    const int b = idx / NN;
    const int n = idx % NN;
    int f = g_first[b];
    if (f == INT_MAX) f = 0;   // all-masked: reference argmax(~mask) = 0

    const size_t src = (size_t)b * 3 * NN + f;
    const size_t dst = (size_t)b * 3 * NN + n;

    out[OFF_U + dst]          = out[OFF_U + src];
    out[OFF_U + dst + NN]     = out[OFF_U + src + NN];
    out[OFF_U + dst + 2 * NN] = out[OFF_U + src + 2 * NN];
    out[OFF_C + dst]          = out[OFF_C + src];
    out[OFF_C + dst + NN]     = out[OFF_C + src + NN];
    out[OFF_C + dst + 2 * NN] = out[OFF_C + src + 2 * NN];
    out[OFF_P + (size_t)b * NN + n] = out[OFF_P + (size_t)b * NN + f];
}

extern "C" void kernel_launch(void* const* d_in, const int* in_sizes, int n_in,
                              void* d_out, int out_size)
{
    const float* center  = (const float*)d_in[0];   // [B,3,N]
    const float* context = (const float*)d_in[1];   // [B,3,M]
    float* out = (float*)d_out;

    surf_scan_kernel<<<BB * BPB * SPLIT, TPB>>>(center, context);
    surf_merge_kernel<<<(BB * NN + 255) / 256, 256>>>(context, out);
    surf_fix_kernel<<<(BB * NN + 255) / 256, 256>>>(out);
}

// round 11
// speedup vs baseline: 1.0584x; 1.0584x over previous
#include <cuda_runtime.h>
#include <math.h>
#include <limits.h>

// Problem constants (fixed by the reference setup_inputs)
#define BB    4
#define NN    8192
#define MM    8192
#define TPB   256
#define SPLIT 8
#define CH    (MM / SPLIT)            // 1024 context points per chunk
#define BPB   (NN / TPB)              // 32 query-blocks per batch

// Output layout: [unit BB*3*NN][cen BB*3*NN][pos BB*NN]
#define OFF_U 0
#define OFF_C (BB * 3 * NN)
#define OFF_P (2 * BB * 3 * NN)

// Scratch (allocation-free: __device__ globals)
__device__ float g_pd[3 * SPLIT * BB * NN];
__device__ int   g_pi[3 * SPLIT * BB * NN];
__device__ unsigned char g_mask[BB * NN];
__device__ int g_first[BB];

#define PD(k, s, q) g_pd[(((k) * SPLIT + (s)) * (BB * NN)) + (q)]
#define PI(k, s, q) g_pi[(((k) * SPLIT + (s)) * (BB * NN)) + (q)]

// ---- packed f32x2 helpers (Blackwell sm_100+): mul/add/fma only ----
typedef unsigned long long u64;

__device__ __forceinline__ u64 f2pk(float lo, float hi) {
    u64 r;
    asm("mov.b64 %0, {%1, %2};" : "=l"(r)
        : "r"(__float_as_uint(lo)), "r"(__float_as_uint(hi)));
    return r;
}
__device__ __forceinline__ void f2un(u64 v, float& lo, float& hi) {
    unsigned a, b;
    asm("mov.b64 {%0, %1}, %2;" : "=r"(a), "=r"(b) : "l"(v));
    lo = __uint_as_float(a); hi = __uint_as_float(b);
}
__device__ __forceinline__ u64 mul2(u64 a, u64 b) {
    u64 r; asm("mul.rn.f32x2 %0, %1, %2;" : "=l"(r) : "l"(a), "l"(b)); return r;
}
__device__ __forceinline__ u64 add2(u64 a, u64 b) {
    u64 r; asm("add.rn.f32x2 %0, %1, %2;" : "=l"(r) : "l"(a), "l"(b)); return r;
}
__device__ __forceinline__ u64 fma2(u64 a, u64 b, u64 c) {
    u64 r; asm("fma.rn.f32x2 %0, %1, %2, %3;" : "=l"(r) : "l"(a), "l"(b), "l"(c)); return r;
}

// Branchless stable top-3 insert (FSETP+SEL). Strict '<' keeps the
// earlier-inserted entry on exact ties => apply in ascending-j order,
// matching lax.top_k.
#define INSB(d, jj) {                                                        \
    bool lt2 = (d) < d2, lt1 = (d) < d1, lt0 = (d) < d0;                     \
    float nd2 = lt1 ? d1 : (d);  int ni2 = lt1 ? i1 : (jj);                  \
    float nd1 = lt0 ? d0 : (d);  int ni1 = lt0 ? i0 : (jj);                  \
    d2 = lt2 ? nd2 : d2;  i2 = lt2 ? ni2 : i2;                               \
    d1 = lt1 ? nd1 : d1;  i1 = lt1 ? ni1 : i1;                               \
    d0 = lt0 ? (d) : d0;  i0 = lt0 ? (jj) : i0;                              \
}

// Quad insert with single-candidate fast path (jbase = index of first point)
#define QUAD_INSERT(da, db, dc, dd, jbase) {                                 \
    bool pa = (da) < d2, pb = (db) < d2, pc = (dc) < d2, pd = (dd) < d2;     \
    int cnt = (int)pa + (int)pb + (int)pc + (int)pd;                         \
    if (cnt == 1) {                                                          \
        float ds = pa ? (da) : (pb ? (db) : (pc ? (dc) : (dd)));             \
        int   js = pa ? (jbase) : (pb ? (jbase) + 1                          \
                                      : (pc ? (jbase) + 2 : (jbase) + 3));   \
        INSB(ds, js);                                                        \
    } else if (cnt > 1) {                                                    \
        INSB(da, (jbase));                                                   \
        INSB(db, (jbase) + 1);                                               \
        INSB(dc, (jbase) + 2);                                               \
        INSB(dd, (jbase) + 3);                                               \
    }                                                                        \
}

__global__ void __launch_bounds__(TPB)
surf_scan_kernel(const float* __restrict__ center,
                 const float* __restrict__ context)
{
    // Interleaved packed layout: per point-pair p (points 2p, 2p+1),
    // sD[4p..4p+3] = { (x0,x1), (y0,y1), (z0,z1), (w0,w1) }  (32 bytes).
    __shared__ __align__(16) u64 sD[(CH / 2) * 4];   // 16 KB

    // One-time scratch init for this replay (merge runs after scan completes)
    if (blockIdx.x < BB && threadIdx.x == 0) g_first[blockIdx.x] = INT_MAX;

    // blockIdx.x = ((b * BPB) + qb) * SPLIT + s
    const int s  = blockIdx.x % SPLIT;
    const int r  = blockIdx.x / SPLIT;
    const int qb = r % BPB;
    const int b  = r / BPB;
    const int j0 = s * CH;

    // Load phase: pack into interleaved f32x2 words (8-byte granular writes)
    const float* ctx = context + (size_t)b * 3 * MM;
    for (int j = threadIdx.x; j < CH; j += TPB) {
        float x = ctx[j0 + j];
        float y = ctx[MM + j0 + j];
        float z = ctx[2 * MM + j0 + j];
        float w = x * x + y * y + z * z;
        const int p = j >> 1, l = j & 1;
        float* f = (float*)&sD[4 * p];
        f[l]     = x;   // (x0,x1)
        f[2 + l] = y;   // (y0,y1)
        f[4 + l] = z;   // (z0,z1)
        f[6 + l] = w;   // (w0,w1)
    }
    __syncthreads();

    // This thread's query point
    const int n = qb * TPB + threadIdx.x;
    const float* cenp = center + (size_t)b * 3 * NN;
    const float qx = cenp[n];
    const float qy = cenp[NN + n];
    const float qz = cenp[2 * NN + n];
    const float cn = qx * qx + qy * qy + qz * qz;

    const u64 QX2  = f2pk(qx, qx);
    const u64 QY2  = f2pk(qy, qy);
    const u64 QZ2  = f2pk(qz, qz);
    const u64 CN2  = f2pk(cn, cn);
    const u64 NEG2 = f2pk(-2.0f, -2.0f);

    float d0 = INFINITY, d1 = INFINITY, d2 = INFINITY;
    int   i0 = 0, i1 = 0, i2 = 0;

    const ulonglong2* sV = (const ulonglong2*)sD;

    #pragma unroll 2
    for (int p = 0; p < CH / 2; p += 4) {     // 8 points per iteration
        ulonglong2 a0 = sV[2 * p];            // {x01, y01}
        ulonglong2 a1 = sV[2 * p + 1];        // {z01, w01}
        ulonglong2 a2 = sV[2 * p + 2];        // {x23, y23}
        ulonglong2 a3 = sV[2 * p + 3];        // {z23, w23}
        ulonglong2 a4 = sV[2 * p + 4];        // {x45, y45}
        ulonglong2 a5 = sV[2 * p + 5];        // {z45, w45}
        ulonglong2 a6 = sV[2 * p + 6];        // {x67, y67}
        ulonglong2 a7 = sV[2 * p + 7];        // {z67, w67}

        // d = (cn + |p|^2) - 2*dot — identical op sequence to prior rounds
        u64 t0 = mul2(QX2, a0.x);
        t0 = fma2(QY2, a0.y, t0);
        t0 = fma2(QZ2, a1.x, t0);
        u64 dp0 = fma2(NEG2, t0, add2(CN2, a1.y));

        u64 t1 = mul2(QX2, a2.x);
        t1 = fma2(QY2, a2.y, t1);
        t1 = fma2(QZ2, a3.x, t1);
        u64 dp1 = fma2(NEG2, t1, add2(CN2, a3.y));

        u64 t2 = mul2(QX2, a4.x);
        t2 = fma2(QY2, a4.y, t2);
        t2 = fma2(QZ2, a5.x, t2);
        u64 dp2 = fma2(NEG2, t2, add2(CN2, a5.y));

        u64 t3 = mul2(QX2, a6.x);
        t3 = fma2(QY2, a6.y, t3);
        t3 = fma2(QZ2, a7.x, t3);
        u64 dp3 = fma2(NEG2, t3, add2(CN2, a7.y));

        float e0, e1, e2x_, e3, e4, e5, e6, e7;
        f2un(dp0, e0, e1);
        f2un(dp1, e2x_, e3);
        f2un(dp2, e4, e5);
        f2un(dp3, e6, e7);

        // Two quad-mins + combined test: one branch per 8 points
        float m0 = fminf(fminf(e0, e1), fminf(e2x_, e3));
        float m1 = fminf(fminf(e4, e5), fminf(e6, e7));

        if (fminf(m0, m1) < d2) {             // rare (~8% of groups)
            const int jj = j0 + 2 * p;
            if (m0 < d2) { QUAD_INSERT(e0, e1, e2x_, e3, jj); }
            if (m1 < d2) { QUAD_INSERT(e4, e5, e6, e7, jj + 4); }
        }
    }

    const int q = b * NN + n;
    PD(0, s, q) = d0;  PI(0, s, q) = i0;
    PD(1, s, q) = d1;  PI(1, s, q) = i1;
    PD(2, s, q) = d2;  PI(2, s, q) = i2;
}

// Merge SPLIT partial triples per query, epilogue, mask, first-good-row.
__global__ void __launch_bounds__(256)
surf_merge_kernel(const float* __restrict__ context,
                  float* __restrict__ out)
{
    const int q = blockIdx.x * blockDim.x + threadIdx.x;
    if (q >= BB * NN) return;
    const int b = q / NN;
    const int n = q % NN;

    float d0 = INFINITY, d1 = INFINITY, d2 = INFINITY;
    int   i0 = 0, i1 = 0, i2 = 0;

    // Ascending split order + rank order -> exact global-scan tie semantics.
    #pragma unroll
    for (int s = 0; s < SPLIT; s++) {
        #pragma unroll
        for (int k = 0; k < 3; k++) {
            float d  = PD(k, s, q);
            int   jj = PI(k, s, q);
            INSB(d, jj);
        }
    }

    const float* ctx = context + (size_t)b * 3 * MM;
    float g0x = ctx[i0], g0y = ctx[MM + i0], g0z = ctx[2 * MM + i0];
    float g1x = ctx[i1], g1y = ctx[MM + i1], g1z = ctx[2 * MM + i1];
    float g2x = ctx[i2], g2y = ctx[MM + i2], g2z = ctx[2 * MM + i2];

    float e1x = g1x - g0x, e1y = g1y - g0y, e1z = g1z - g0z;
    float e2x = g2x - g0x, e2y = g2y - g0y, e2z = g2z - g0z;

    float nx = e1y * e2z - e1z * e2y;
    float ny = e1z * e2x - e1x * e2z;
    float nz = e1x * e2y - e1y * e2x;

    float nrm = sqrtf(nx * nx + ny * ny + nz * nz);
    float ux = nx / nrm;
    float uy = ny / nrm;
    float uz = nz / nrm;

    float sg = (ux > 0.0f) ? 1.0f : -1.0f;   // NaN compares false -> -1
    ux *= sg; uy *= sg; uz *= sg;

    float cx = (g0x + g1x + g2x) / 3.0f;
    float cy = (g0y + g1y + g2y) / 3.0f;
    float cz = (g0z + g1z + g2z) / 3.0f;

    float pos = (ux * cx + uy * cy + uz * cz) / sqrtf(3.0f);

    bool bad = (ux != ux) || (uy != uy) || (uz != uz);
    g_mask[q] = bad ? 1 : 0;

    // first non-NaN row per batch: warp-reduce then one atomic per warp.
    // Block covers consecutive q within ONE batch (NN % 256 == 0).
    int v = bad ? INT_MAX : n;
    int wmin = __reduce_min_sync(0xffffffffu, v);
    if ((threadIdx.x & 31) == 0 && wmin != INT_MAX)
        atomicMin(&g_first[b], wmin);

    const size_t base = (size_t)b * 3 * NN + n;
    out[OFF_U + base]          = ux;
    out[OFF_U + base + NN]     = uy;
    out[OFF_U + base + 2 * NN] = uz;
    out[OFF_C + base]          = cx;
    out[OFF_C + base + NN]     = cy;
    out[OFF_C + base + 2 * NN] = cz;
    out[OFF_P + (size_t)b * NN + n] = pos;
}

// Rewrite masked rows with the first non-NaN row's values
__global__ void surf_fix_kernel(float* __restrict__ out)
{
    const int idx = blockIdx.x * blockDim.x + threadIdx.x;
    if (idx >= BB * NN) return;
    if (!g_mask[idx]) return;

    const int b = idx / NN;
    const int n = idx % NN;
    int f = g_first[b];
    if (f == INT_MAX) f = 0;   // all-masked: reference argmax(~mask) = 0

    const size_t src = (size_t)b * 3 * NN + f;
    const size_t dst = (size_t)b * 3 * NN + n;

    out[OFF_U + dst]          = out[OFF_U + src];
    out[OFF_U + dst + NN]     = out[OFF_U + src + NN];
    out[OFF_U + dst + 2 * NN] = out[OFF_U + src + 2 * NN];
    out[OFF_C + dst]          = out[OFF_C + src];
    out[OFF_C + dst + NN]     = out[OFF_C + src + NN];
    out[OFF_C + dst + 2 * NN] = out[OFF_C + src + 2 * NN];
    out[OFF_P + (size_t)b * NN + n] = out[OFF_P + (size_t)b * NN + f];
}

extern "C" void kernel_launch(void* const* d_in, const int* in_sizes, int n_in,
                              void* d_out, int out_size)
{
    const float* center  = (const float*)d_in[0];   // [B,3,N]
    const float* context = (const float*)d_in[1];   // [B,3,M]
    float* out = (float*)d_out;

    surf_scan_kernel<<<BB * BPB * SPLIT, TPB>>>(center, context);
    surf_merge_kernel<<<(BB * NN + 255) / 256, 256>>>(context, out);
    surf_fix_kernel<<<(BB * NN + 255) / 256, 256>>>(out);
}

// round 13
// speedup vs baseline: 1.0673x; 1.0084x over previous
#include <cuda_runtime.h>
#include <math.h>
#include <limits.h>

// Problem constants (fixed by the reference setup_inputs)
#define BB    4
#define NN    8192
#define MM    8192
#define TPB   128
#define SPLIT 8
#define CH    (MM / SPLIT)            // 1024 context points per chunk
#define BPB   (NN / TPB)              // 64 query-blocks per batch

// Output layout: [unit BB*3*NN][cen BB*3*NN][pos BB*NN]
#define OFF_U 0
#define OFF_C (BB * 3 * NN)
#define OFF_P (2 * BB * 3 * NN)

// Scratch (allocation-free: __device__ globals)
__device__ float g_pd[3 * SPLIT * BB * NN];
__device__ int   g_pi[3 * SPLIT * BB * NN];
__device__ unsigned char g_mask[BB * NN];
__device__ int g_first[BB];

#define PD(k, s, q) g_pd[(((k) * SPLIT + (s)) * (BB * NN)) + (q)]
#define PI(k, s, q) g_pi[(((k) * SPLIT + (s)) * (BB * NN)) + (q)]

// ---- packed f32x2 helpers (Blackwell sm_100+): mul/add/fma only ----
typedef unsigned long long u64;

__device__ __forceinline__ u64 f2pk(float lo, float hi) {
    u64 r;
    asm("mov.b64 %0, {%1, %2};" : "=l"(r)
        : "r"(__float_as_uint(lo)), "r"(__float_as_uint(hi)));
    return r;
}
__device__ __forceinline__ void f2un(u64 v, float& lo, float& hi) {
    unsigned a, b;
    asm("mov.b64 {%0, %1}, %2;" : "=r"(a), "=r"(b) : "l"(v));
    lo = __uint_as_float(a); hi = __uint_as_float(b);
}
__device__ __forceinline__ u64 mul2(u64 a, u64 b) {
    u64 r; asm("mul.rn.f32x2 %0, %1, %2;" : "=l"(r) : "l"(a), "l"(b)); return r;
}
__device__ __forceinline__ u64 add2(u64 a, u64 b) {
    u64 r; asm("add.rn.f32x2 %0, %1, %2;" : "=l"(r) : "l"(a), "l"(b)); return r;
}
__device__ __forceinline__ u64 fma2(u64 a, u64 b, u64 c) {
    u64 r; asm("fma.rn.f32x2 %0, %1, %2, %3;" : "=l"(r) : "l"(a), "l"(b), "l"(c)); return r;
}

// Branchless stable top-3 insert (FSETP+SEL). Strict '<' keeps the
// earlier-inserted entry on exact ties => apply in ascending-j order,
// matching lax.top_k.
#define INSB(d, jj) {                                                        \
    bool lt2 = (d) < d2, lt1 = (d) < d1, lt0 = (d) < d0;                     \
    float nd2 = lt1 ? d1 : (d);  int ni2 = lt1 ? i1 : (jj);                  \
    float nd1 = lt0 ? d0 : (d);  int ni1 = lt0 ? i0 : (jj);                  \
    d2 = lt2 ? nd2 : d2;  i2 = lt2 ? ni2 : i2;                               \
    d1 = lt1 ? nd1 : d1;  i1 = lt1 ? ni1 : i1;                               \
    d0 = lt0 ? (d) : d0;  i0 = lt0 ? (jj) : i0;                              \
}

__global__ void __launch_bounds__(TPB)
surf_scan_kernel(const float* __restrict__ center,
                 const float* __restrict__ context)
{
    // Interleaved packed layout: per point-pair p (points 2p, 2p+1),
    // sD[4p..4p+3] = { (x0,x1), (y0,y1), (z0,z1), (w0,w1) }  (32 bytes).
    __shared__ __align__(16) u64 sD[(CH / 2) * 4];   // 16 KB

    // One-time scratch init for this replay (merge runs after scan completes)
    if (blockIdx.x < BB && threadIdx.x == 0) g_first[blockIdx.x] = INT_MAX;

    // blockIdx.x = ((b * BPB) + qb) * SPLIT + s
    const int s  = blockIdx.x % SPLIT;
    const int r  = blockIdx.x / SPLIT;
    const int qb = r % BPB;
    const int b  = r / BPB;
    const int j0 = s * CH;

    // Load phase: pack into interleaved f32x2 words (8-byte granular writes)
    const float* ctx = context + (size_t)b * 3 * MM;
    for (int j = threadIdx.x; j < CH; j += TPB) {
        float x = ctx[j0 + j];
        float y = ctx[MM + j0 + j];
        float z = ctx[2 * MM + j0 + j];
        float w = x * x + y * y + z * z;
        const int p = j >> 1, l = j & 1;
        float* f = (float*)&sD[4 * p];
        f[l]     = x;   // (x0,x1)
        f[2 + l] = y;   // (y0,y1)
        f[4 + l] = z;   // (z0,z1)
        f[6 + l] = w;   // (w0,w1)
    }
    __syncthreads();

    // This thread's query point
    const int n = qb * TPB + threadIdx.x;
    const float* cenp = center + (size_t)b * 3 * NN;
    const float qx = cenp[n];
    const float qy = cenp[NN + n];
    const float qz = cenp[2 * NN + n];
    const float cn = qx * qx + qy * qy + qz * qz;

    const u64 QX2  = f2pk(qx, qx);
    const u64 QY2  = f2pk(qy, qy);
    const u64 QZ2  = f2pk(qz, qz);
    const u64 CN2  = f2pk(cn, cn);
    const u64 NEG2 = f2pk(-2.0f, -2.0f);

    float d0 = INFINITY, d1 = INFINITY, d2 = INFINITY;
    int   i0 = 0, i1 = 0, i2 = 0;

    const ulonglong2* sV = (const ulonglong2*)sD;

    #pragma unroll 4
    for (int p = 0; p < CH / 2; p += 2) {     // 4 points per iteration
        ulonglong2 a0 = sV[2 * p];            // {x01, y01}
        ulonglong2 a1 = sV[2 * p + 1];        // {z01, w01}
        ulonglong2 a2 = sV[2 * p + 2];        // {x23, y23}
        ulonglong2 a3 = sV[2 * p + 3];        // {z23, w23}

        // d = (cn + |p|^2) - 2*dot — identical op sequence to prior rounds
        u64 t0 = mul2(QX2, a0.x);
        t0 = fma2(QY2, a0.y, t0);
        t0 = fma2(QZ2, a1.x, t0);
        u64 dp0 = fma2(NEG2, t0, add2(CN2, a1.y));

        u64 t1 = mul2(QX2, a2.x);
        t1 = fma2(QY2, a2.y, t1);
        t1 = fma2(QZ2, a3.x, t1);
        u64 dp1 = fma2(NEG2, t1, add2(CN2, a3.y));

        float da, db, dc, dd;
        f2un(dp0, da, db);
        f2un(dp1, dc, dd);

        float m = fminf(fminf(da, db), fminf(dc, dd));
        if (m < d2) {                         // rare (~5% of groups)
            const int jj = j0 + 2 * p;
            bool pa = da < d2, pb = db < d2, pc = dc < d2, pd = dd < d2;
            int cnt = (int)pa + (int)pb + (int)pc + (int)pd;
            if (cnt == 1) {
                // exactly one candidate: order-independent single insert
                float ds = pa ? da : (pb ? db : (pc ? dc : dd));
                int   js = pa ? jj : (pb ? jj + 1 : (pc ? jj + 2 : jj + 3));
                INSB(ds, js);
            } else {
                // ascending-j sequential inserts: exact tie semantics
                INSB(da, jj);
                INSB(db, jj + 1);
                INSB(dc, jj + 2);
                INSB(dd, jj + 3);
            }
        }
    }

    const int q = b * NN + n;
    PD(0, s, q) = d0;  PI(0, s, q) = i0;
    PD(1, s, q) = d1;  PI(1, s, q) = i1;
    PD(2, s, q) = d2;  PI(2, s, q) = i2;
}

// Merge SPLIT partial triples per query, epilogue, mask, first-good-row.
__global__ void __launch_bounds__(256)
surf_merge_kernel(const float* __restrict__ context,
                  float* __restrict__ out)
{
    const int q = blockIdx.x * blockDim.x + threadIdx.x;
    if (q >= BB * NN) return;
    const int b = q / NN;
    const int n = q % NN;

    float d0 = INFINITY, d1 = INFINITY, d2 = INFINITY;
    int   i0 = 0, i1 = 0, i2 = 0;

    // Ascending split order + rank order -> exact global-scan tie semantics.
    #pragma unroll
    for (int s = 0; s < SPLIT; s++) {
        #pragma unroll
        for (int k = 0; k < 3; k++) {
            float d  = PD(k, s, q);
            int   jj = PI(k, s, q);
            INSB(d, jj);
        }
    }

    const float* ctx = context + (size_t)b * 3 * MM;
    float g0x = ctx[i0], g0y = ctx[MM + i0], g0z = ctx[2 * MM + i0];
    float g1x = ctx[i1], g1y = ctx[MM + i1], g1z = ctx[2 * MM + i1];
    float g2x = ctx[i2], g2y = ctx[MM + i2], g2z = ctx[2 * MM + i2];

    float e1x = g1x - g0x, e1y = g1y - g0y, e1z = g1z - g0z;
    float e2x = g2x - g0x, e2y = g2y - g0y, e2z = g2z - g0z;

    float nx = e1y * e2z - e1z * e2y;
    float ny = e1z * e2x - e1x * e2z;
    float nz = e1x * e2y - e1y * e2x;

    float nrm = sqrtf(nx * nx + ny * ny + nz * nz);
    float ux = nx / nrm;
    float uy = ny / nrm;
    float uz = nz / nrm;

    float sg = (ux > 0.0f) ? 1.0f : -1.0f;   // NaN compares false -> -1
    ux *= sg; uy *= sg; uz *= sg;

    float cx = (g0x + g1x + g2x) / 3.0f;
    float cy = (g0y + g1y + g2y) / 3.0f;
    float cz = (g0z + g1z + g2z) / 3.0f;

    float pos = (ux * cx + uy * cy + uz * cz) / sqrtf(3.0f);

    bool bad = (ux != ux) || (uy != uy) || (uz != uz);
    g_mask[q] = bad ? 1 : 0;

    // first non-NaN row per batch: warp-reduce then one atomic per warp.
    // Block covers consecutive q within ONE batch (NN % 256 == 0).
    int v = bad ? INT_MAX : n;
    int wmin = __reduce_min_sync(0xffffffffu, v);
    if ((threadIdx.x & 31) == 0 && wmin != INT_MAX)
        atomicMin(&g_first[b], wmin);

    const size_t base = (size_t)b * 3 * NN + n;
    out[OFF_U + base]          = ux;
    out[OFF_U + base + NN]     = uy;
    out[OFF_U + base + 2 * NN] = uz;
    out[OFF_C + base]          = cx;
    out[OFF_C + base + NN]     = cy;
    out[OFF_C + base + 2 * NN] = cz;
    out[OFF_P + (size_t)b * NN + n] = pos;
}

// Rewrite masked rows with the first non-NaN row's values
__global__ void surf_fix_kernel(float* __restrict__ out)
{
    const int idx = blockIdx.x * blockDim.x + threadIdx.x;
    if (idx >= BB * NN) return;
    if (!g_mask[idx]) return;

    const int b = idx / NN;
    const int n = idx % NN;
    int f = g_first[b];
    if (f == INT_MAX) f = 0;   // all-masked: reference argmax(~mask) = 0

    const size_t src = (size_t)b * 3 * NN + f;
    const size_t dst = (size_t)b * 3 * NN + n;

    out[OFF_U + dst]          = out[OFF_U + src];
    out[OFF_U + dst + NN]     = out[OFF_U + src + NN];
    out[OFF_U + dst + 2 * NN] = out[OFF_U + src + 2 * NN];
    out[OFF_C + dst]          = out[OFF_C + src];
    out[OFF_C + dst + NN]     = out[OFF_C + src + NN];
    out[OFF_C + dst + 2 * NN] = out[OFF_C + src + 2 * NN];
    out[OFF_P + (size_t)b * NN + n] = out[OFF_P + (size_t)b * NN + f];
}

extern "C" void kernel_launch(void* const* d_in, const int* in_sizes, int n_in,
                              void* d_out, int out_size)
{
    const float* center  = (const float*)d_in[0];   // [B,3,N]
    const float* context = (const float*)d_in[1];   // [B,3,M]
    float* out = (float*)d_out;

    surf_scan_kernel<<<BB * BPB * SPLIT, TPB>>>(center, context);
    surf_merge_kernel<<<(BB * NN + 255) / 256, 256>>>(context, out);
    surf_fix_kernel<<<(BB * NN + 255) / 256, 256>>>(out);
}

// round 14
// speedup vs baseline: 1.1352x; 1.0636x over previous
#include <cuda_runtime.h>
#include <math.h>
#include <limits.h>

// Problem constants (fixed by the reference setup_inputs)
#define BB    4
#define NN    8192
#define MM    8192
#define TPB   256
#define SPLIT 8
#define CH    (MM / SPLIT)            // 1024 context points per chunk
#define BPB   (NN / TPB)              // 32 query-blocks per batch

// Output layout: [unit BB*3*NN][cen BB*3*NN][pos BB*NN]
#define OFF_U 0
#define OFF_C (BB * 3 * NN)
#define OFF_P (2 * BB * 3 * NN)

// Scratch (allocation-free: __device__ globals)
__device__ float g_pd[3 * SPLIT * BB * NN];
__device__ int   g_pi[3 * SPLIT * BB * NN];
__device__ unsigned char g_mask[BB * NN];
__device__ int g_first[BB];

#define PD(k, s, q) g_pd[(((k) * SPLIT + (s)) * (BB * NN)) + (q)]
#define PI(k, s, q) g_pi[(((k) * SPLIT + (s)) * (BB * NN)) + (q)]

// ---- packed f32x2 helpers (Blackwell sm_100+): mul/add/fma only ----
typedef unsigned long long u64;

__device__ __forceinline__ u64 f2pk(float lo, float hi) {
    u64 r;
    asm("mov.b64 %0, {%1, %2};" : "=l"(r)
        : "r"(__float_as_uint(lo)), "r"(__float_as_uint(hi)));
    return r;
}
__device__ __forceinline__ void f2un(u64 v, float& lo, float& hi) {
    unsigned a, b;
    asm("mov.b64 {%0, %1}, %2;" : "=r"(a), "=r"(b) : "l"(v));
    lo = __uint_as_float(a); hi = __uint_as_float(b);
}
__device__ __forceinline__ u64 add2(u64 a, u64 b) {
    u64 r; asm("add.rn.f32x2 %0, %1, %2;" : "=l"(r) : "l"(a), "l"(b)); return r;
}
__device__ __forceinline__ u64 fma2(u64 a, u64 b, u64 c) {
    u64 r; asm("fma.rn.f32x2 %0, %1, %2, %3;" : "=l"(r) : "l"(a), "l"(b), "l"(c)); return r;
}

// Branchless stable top-3 insert (FSETP+SEL). Strict '<' keeps the
// earlier-inserted entry on exact ties => apply in ascending-j order,
// matching lax.top_k.
#define INSB(d, jj) {                                                        \
    bool lt2 = (d) < d2, lt1 = (d) < d1, lt0 = (d) < d0;                     \
    float nd2 = lt1 ? d1 : (d);  int ni2 = lt1 ? i1 : (jj);                  \
    float nd1 = lt0 ? d0 : (d);  int ni1 = lt0 ? i0 : (jj);                  \
    d2 = lt2 ? nd2 : d2;  i2 = lt2 ? ni2 : i2;                               \
    d1 = lt1 ? nd1 : d1;  i1 = lt1 ? ni1 : i1;                               \
    d0 = lt0 ? (d) : d0;  i0 = lt0 ? (jj) : i0;                              \
}

__global__ void __launch_bounds__(TPB)
surf_scan_kernel(const float* __restrict__ center,
                 const float* __restrict__ context)
{
    // Interleaved packed layout: per point-pair p (points 2p, 2p+1),
    // sD[4p..4p+3] = { (x0,x1), (y0,y1), (z0,z1), (w0,w1) }  (32 bytes).
    __shared__ __align__(16) u64 sD[(CH / 2) * 4];   // 16 KB

    // One-time scratch init for this replay (merge runs after scan completes)
    if (blockIdx.x < BB && threadIdx.x == 0) g_first[blockIdx.x] = INT_MAX;

    // blockIdx.x = ((b * BPB) + qb) * SPLIT + s
    const int s  = blockIdx.x % SPLIT;
    const int r  = blockIdx.x / SPLIT;
    const int qb = r % BPB;
    const int b  = r / BPB;
    const int j0 = s * CH;

    // Load phase: pack into interleaved f32x2 words (8-byte granular writes)
    const float* ctx = context + (size_t)b * 3 * MM;
    for (int j = threadIdx.x; j < CH; j += TPB) {
        float x = ctx[j0 + j];
        float y = ctx[MM + j0 + j];
        float z = ctx[2 * MM + j0 + j];
        float w = x * x + y * y + z * z;
        const int p = j >> 1, l = j & 1;
        float* f = (float*)&sD[4 * p];
        f[l]     = x;   // (x0,x1)
        f[2 + l] = y;   // (y0,y1)
        f[4 + l] = z;   // (z0,z1)
        f[6 + l] = w;   // (w0,w1)
    }
    __syncthreads();

    // This thread's query point
    const int n = qb * TPB + threadIdx.x;
    const float* cenp = center + (size_t)b * 3 * NN;
    const float qx = cenp[n];
    const float qy = cenp[NN + n];
    const float qz = cenp[2 * NN + n];
    const float cn = qx * qx + qy * qy + qz * qz;

    // Negated-doubled query constants: d = cn + w - 2*dot computed as
    // fma(-2qz, z, fma(-2qy, y, fma(-2qx, x, cn + w)))  -> 4 packed ops/pair
    const u64 QXn = f2pk(-2.0f * qx, -2.0f * qx);
    const u64 QYn = f2pk(-2.0f * qy, -2.0f * qy);
    const u64 QZn = f2pk(-2.0f * qz, -2.0f * qz);
    const u64 CN2 = f2pk(cn, cn);

    float d0 = INFINITY, d1 = INFINITY, d2 = INFINITY;
    int   i0 = 0, i1 = 0, i2 = 0;

    const ulonglong2* sV = (const ulonglong2*)sD;

    #pragma unroll 4
    for (int p = 0; p < CH / 2; p += 2) {     // 4 points per iteration
        ulonglong2 a0 = sV[2 * p];            // {x01, y01}
        ulonglong2 a1 = sV[2 * p + 1];        // {z01, w01}
        ulonglong2 a2 = sV[2 * p + 2];        // {x23, y23}
        ulonglong2 a3 = sV[2 * p + 3];        // {z23, w23}

        u64 t0 = add2(CN2, a1.y);             // cn + w
        t0 = fma2(QXn, a0.x, t0);
        t0 = fma2(QYn, a0.y, t0);
        u64 dp0 = fma2(QZn, a1.x, t0);

        u64 t1 = add2(CN2, a3.y);
        t1 = fma2(QXn, a2.x, t1);
        t1 = fma2(QYn, a2.y, t1);
        u64 dp1 = fma2(QZn, a3.x, t1);

        float da, db, dc, dd;
        f2un(dp0, da, db);
        f2un(dp1, dc, dd);

        float m = fminf(fminf(da, db), fminf(dc, dd));
        if (m < d2) {                         // rare (~5% of groups)
            const int jj = j0 + 2 * p;
            bool pa = da < d2, pb = db < d2, pc = dc < d2, pd = dd < d2;
            int cnt = (int)pa + (int)pb + (int)pc + (int)pd;
            if (cnt == 1) {
                // exactly one candidate: order-independent single insert
                float ds = pa ? da : (pb ? db : (pc ? dc : dd));
                int   js = pa ? jj : (pb ? jj + 1 : (pc ? jj + 2 : jj + 3));
                INSB(ds, js);
            } else {
                // ascending-j sequential inserts: exact tie semantics
                INSB(da, jj);
                INSB(db, jj + 1);
                INSB(dc, jj + 2);
                INSB(dd, jj + 3);
            }
        }
    }

    const int q = b * NN + n;
    PD(0, s, q) = d0;  PI(0, s, q) = i0;
    PD(1, s, q) = d1;  PI(1, s, q) = i1;
    PD(2, s, q) = d2;  PI(2, s, q) = i2;
}

// Merge SPLIT partial triples per query, epilogue, mask, first-good-row.
__global__ void __launch_bounds__(256)
surf_merge_kernel(const float* __restrict__ context,
                  float* __restrict__ out)
{
    const int q = blockIdx.x * blockDim.x + threadIdx.x;
    if (q >= BB * NN) return;
    const int b = q / NN;
    const int n = q % NN;

    float d0 = INFINITY, d1 = INFINITY, d2 = INFINITY;
    int   i0 = 0, i1 = 0, i2 = 0;

    // Ascending split order + rank order -> exact global-scan tie semantics.
    #pragma unroll
    for (int s = 0; s < SPLIT; s++) {
        #pragma unroll
        for (int k = 0; k < 3; k++) {
            float d  = PD(k, s, q);
            int   jj = PI(k, s, q);
            INSB(d, jj);
        }
    }

    const float* ctx = context + (size_t)b * 3 * MM;
    float g0x = ctx[i0], g0y = ctx[MM + i0], g0z = ctx[2 * MM + i0];
    float g1x = ctx[i1], g1y = ctx[MM + i1], g1z = ctx[2 * MM + i1];
    float g2x = ctx[i2], g2y = ctx[MM + i2], g2z = ctx[2 * MM + i2];

    float e1x = g1x - g0x, e1y = g1y - g0y, e1z = g1z - g0z;
    float e2x = g2x - g0x, e2y = g2y - g0y, e2z = g2z - g0z;

    float nx = e1y * e2z - e1z * e2y;
    float ny = e1z * e2x - e1x * e2z;
    float nz = e1x * e2y - e1y * e2x;

    float nrm = sqrtf(nx * nx + ny * ny + nz * nz);
    float ux = nx / nrm;
    float uy = ny / nrm;
    float uz = nz / nrm;

    float sg = (ux > 0.0f) ? 1.0f : -1.0f;   // NaN compares false -> -1
    ux *= sg; uy *= sg; uz *= sg;

    float cx = (g0x + g1x + g2x) / 3.0f;
    float cy = (g0y + g1y + g2y) / 3.0f;
    float cz = (g0z + g1z + g2z) / 3.0f;

    float pos = (ux * cx + uy * cy + uz * cz) / sqrtf(3.0f);

    bool bad = (ux != ux) || (uy != uy) || (uz != uz);
    g_mask[q] = bad ? 1 : 0;

    // first non-NaN row per batch: warp-reduce then one atomic per warp.
    // Block covers consecutive q within ONE batch (NN % 256 == 0).
    int v = bad ? INT_MAX : n;
    int wmin = __reduce_min_sync(0xffffffffu, v);
    if ((threadIdx.x & 31) == 0 && wmin != INT_MAX)
        atomicMin(&g_first[b], wmin);

    const size_t base = (size_t)b * 3 * NN + n;
    out[OFF_U + base]          = ux;
    out[OFF_U + base + NN]     = uy;
    out[OFF_U + base + 2 * NN] = uz;
    out[OFF_C + base]          = cx;
    out[OFF_C + base + NN]     = cy;
    out[OFF_C + base + 2 * NN] = cz;
    out[OFF_P + (size_t)b * NN + n] = pos;
}

// Rewrite masked rows with the first non-NaN row's values
__global__ void surf_fix_kernel(float* __restrict__ out)
{
    const int idx = blockIdx.x * blockDim.x + threadIdx.x;
    if (idx >= BB * NN) return;
    if (!g_mask[idx]) return;

    const int b = idx / NN;
    const int n = idx % NN;
    int f = g_first[b];
    if (f == INT_MAX) f = 0;   // all-masked: reference argmax(~mask) = 0

    const size_t src = (size_t)b * 3 * NN + f;
    const size_t dst = (size_t)b * 3 * NN + n;

    out[OFF_U + dst]          = out[OFF_U + src];
    out[OFF_U + dst + NN]     = out[OFF_U + src + NN];
    out[OFF_U + dst + 2 * NN] = out[OFF_U + src + 2 * NN];
    out[OFF_C + dst]          = out[OFF_C + src];
    out[OFF_C + dst + NN]     = out[OFF_C + src + NN];
    out[OFF_C + dst + 2 * NN] = out[OFF_C + src + 2 * NN];
    out[OFF_P + (size_t)b * NN + n] = out[OFF_P + (size_t)b * NN + f];
}

extern "C" void kernel_launch(void* const* d_in, const int* in_sizes, int n_in,
                              void* d_out, int out_size)
{
    const float* center  = (const float*)d_in[0];   // [B,3,N]
    const float* context = (const float*)d_in[1];   // [B,3,M]
    float* out = (float*)d_out;

    surf_scan_kernel<<<BB * BPB * SPLIT, TPB>>>(center, context);
    surf_merge_kernel<<<(BB * NN + 255) / 256, 256>>>(context, out);
    surf_fix_kernel<<<(BB * NN + 255) / 256, 256>>>(out);
}

// round 15
// speedup vs baseline: 1.1969x; 1.0544x over previous
#include <cuda_runtime.h>
#include <math.h>
#include <limits.h>

// Problem constants (fixed by the reference setup_inputs)
#define BB    4
#define NN    8192
#define MM    8192
#define TPB   256
#define SPLIT 8
#define CH    (MM / SPLIT)            // 1024 context points per chunk
#define BPB   (NN / TPB)              // 32 query-blocks per batch

// Output layout: [unit BB*3*NN][cen BB*3*NN][pos BB*NN]
#define OFF_U 0
#define OFF_C (BB * 3 * NN)
#define OFF_P (2 * BB * 3 * NN)

// Scratch (allocation-free: __device__ globals)
__device__ float g_pd[3 * SPLIT * BB * NN];
__device__ int   g_pi[3 * SPLIT * BB * NN];
__device__ unsigned char g_mask[BB * NN];
__device__ int g_first[BB];

#define PD(k, s, q) g_pd[(((k) * SPLIT + (s)) * (BB * NN)) + (q)]
#define PI(k, s, q) g_pi[(((k) * SPLIT + (s)) * (BB * NN)) + (q)]

// ---- packed f32x2 helpers (Blackwell sm_100+): mul/add/fma only ----
typedef unsigned long long u64;

__device__ __forceinline__ u64 f2pk(float lo, float hi) {
    u64 r;
    asm("mov.b64 %0, {%1, %2};" : "=l"(r)
        : "r"(__float_as_uint(lo)), "r"(__float_as_uint(hi)));
    return r;
}
__device__ __forceinline__ void f2un(u64 v, float& lo, float& hi) {
    unsigned a, b;
    asm("mov.b64 {%0, %1}, %2;" : "=r"(a), "=r"(b) : "l"(v));
    lo = __uint_as_float(a); hi = __uint_as_float(b);
}
__device__ __forceinline__ u64 fma2(u64 a, u64 b, u64 c) {
    u64 r; asm("fma.rn.f32x2 %0, %1, %2, %3;" : "=l"(r) : "l"(a), "l"(b), "l"(c)); return r;
}

// Branchless stable top-3 insert (FSETP+SEL). Strict '<' keeps the
// earlier-inserted entry on exact ties => apply in ascending-j order,
// matching lax.top_k.
#define INSB(d, jj) {                                                        \
    bool lt2 = (d) < d2, lt1 = (d) < d1, lt0 = (d) < d0;                     \
    float nd2 = lt1 ? d1 : (d);  int ni2 = lt1 ? i1 : (jj);                  \
    float nd1 = lt0 ? d0 : (d);  int ni1 = lt0 ? i0 : (jj);                  \
    d2 = lt2 ? nd2 : d2;  i2 = lt2 ? ni2 : i2;                               \
    d1 = lt1 ? nd1 : d1;  i1 = lt1 ? ni1 : i1;                               \
    d0 = lt0 ? (d) : d0;  i0 = lt0 ? (jj) : i0;                              \
}

__global__ void __launch_bounds__(TPB)
surf_scan_kernel(const float* __restrict__ center,
                 const float* __restrict__ context)
{
    // Interleaved packed layout: per point-pair p (points 2p, 2p+1),
    // sD[4p..4p+3] = { (x0,x1), (y0,y1), (z0,z1), (w0,w1) }  (32 bytes).
    __shared__ __align__(16) u64 sD[(CH / 2) * 4];   // 16 KB

    // One-time scratch init for this replay (merge runs after scan completes)
    if (blockIdx.x < BB && threadIdx.x == 0) g_first[blockIdx.x] = INT_MAX;

    // blockIdx.x = ((b * BPB) + qb) * SPLIT + s
    const int s  = blockIdx.x % SPLIT;
    const int r  = blockIdx.x / SPLIT;
    const int qb = r % BPB;
    const int b  = r / BPB;
    const int j0 = s * CH;

    // Load phase: pack into interleaved f32x2 words (8-byte granular writes)
    const float* ctx = context + (size_t)b * 3 * MM;
    for (int j = threadIdx.x; j < CH; j += TPB) {
        float x = ctx[j0 + j];
        float y = ctx[MM + j0 + j];
        float z = ctx[2 * MM + j0 + j];
        float w = x * x + y * y + z * z;
        const int p = j >> 1, l = j & 1;
        float* f = (float*)&sD[4 * p];
        f[l]     = x;   // (x0,x1)
        f[2 + l] = y;   // (y0,y1)
        f[4 + l] = z;   // (z0,z1)
        f[6 + l] = w;   // (w0,w1)
    }
    __syncthreads();

    // This thread's query point
    const int n = qb * TPB + threadIdx.x;
    const float* cenp = center + (size_t)b * 3 * NN;
    const float qx = cenp[n];
    const float qy = cenp[NN + n];
    const float qz = cenp[2 * NN + n];

    // Query-constant shift |c|^2 dropped: ranking of d' = w - 2*dot over
    // context points is identical (exact arithmetic) to d = cn + w - 2*dot.
    // d' = fma(-2qz, z, fma(-2qy, y, fma(-2qx, x, w)))  -> 3 packed ops/pair
    const u64 QXn = f2pk(-2.0f * qx, -2.0f * qx);
    const u64 QYn = f2pk(-2.0f * qy, -2.0f * qy);
    const u64 QZn = f2pk(-2.0f * qz, -2.0f * qz);

    float d0 = INFINITY, d1 = INFINITY, d2 = INFINITY;
    int   i0 = 0, i1 = 0, i2 = 0;

    const ulonglong2* sV = (const ulonglong2*)sD;

    #pragma unroll 4
    for (int p = 0; p < CH / 2; p += 2) {     // 4 points per iteration
        ulonglong2 a0 = sV[2 * p];            // {x01, y01}
        ulonglong2 a1 = sV[2 * p + 1];        // {z01, w01}
        ulonglong2 a2 = sV[2 * p + 2];        // {x23, y23}
        ulonglong2 a3 = sV[2 * p + 3];        // {z23, w23}

        u64 t0 = fma2(QXn, a0.x, a1.y);       // -2qx*x + w
        t0 = fma2(QYn, a0.y, t0);
        u64 dp0 = fma2(QZn, a1.x, t0);

        u64 t1 = fma2(QXn, a2.x, a3.y);
        t1 = fma2(QYn, a2.y, t1);
        u64 dp1 = fma2(QZn, a3.x, t1);

        float da, db, dc, dd;
        f2un(dp0, da, db);
        f2un(dp1, dc, dd);

        float m = fminf(fminf(da, db), fminf(dc, dd));
        if (m < d2) {                         // rare (~5% of groups)
            const int jj = j0 + 2 * p;
            bool pa = da < d2, pb = db < d2, pc = dc < d2, pd = dd < d2;
            int cnt = (int)pa + (int)pb + (int)pc + (int)pd;
            if (cnt == 1) {
                // exactly one candidate: order-independent single insert
                float ds = pa ? da : (pb ? db : (pc ? dc : dd));
                int   js = pa ? jj : (pb ? jj + 1 : (pc ? jj + 2 : jj + 3));
                INSB(ds, js);
            } else {
                // ascending-j sequential inserts: exact tie semantics
                INSB(da, jj);
                INSB(db, jj + 1);
                INSB(dc, jj + 2);
                INSB(dd, jj + 3);
            }
        }
    }

    const int q = b * NN + n;
    PD(0, s, q) = d0;  PI(0, s, q) = i0;
    PD(1, s, q) = d1;  PI(1, s, q) = i1;
    PD(2, s, q) = d2;  PI(2, s, q) = i2;
}

// Merge SPLIT partial triples per query, epilogue, mask, first-good-row.
// Partials are in the d' = w - 2*dot domain (consistent per query).
__global__ void __launch_bounds__(256)
surf_merge_kernel(const float* __restrict__ context,
                  float* __restrict__ out)
{
    const int q = blockIdx.x * blockDim.x + threadIdx.x;
    if (q >= BB * NN) return;
    const int b = q / NN;
    const int n = q % NN;

    float d0 = INFINITY, d1 = INFINITY, d2 = INFINITY;
    int   i0 = 0, i1 = 0, i2 = 0;

    // Ascending split order + rank order -> exact global-scan tie semantics.
    #pragma unroll
    for (int s = 0; s < SPLIT; s++) {
        #pragma unroll
        for (int k = 0; k < 3; k++) {
            float d  = PD(k, s, q);
            int   jj = PI(k, s, q);
            INSB(d, jj);
        }
    }

    const float* ctx = context + (size_t)b * 3 * MM;
    float g0x = ctx[i0], g0y = ctx[MM + i0], g0z = ctx[2 * MM + i0];
    float g1x = ctx[i1], g1y = ctx[MM + i1], g1z = ctx[2 * MM + i1];
    float g2x = ctx[i2], g2y = ctx[MM + i2], g2z = ctx[2 * MM + i2];

    float e1x = g1x - g0x, e1y = g1y - g0y, e1z = g1z - g0z;
    float e2x = g2x - g0x, e2y = g2y - g0y, e2z = g2z - g0z;

    float nx = e1y * e2z - e1z * e2y;
    float ny = e1z * e2x - e1x * e2z;
    float nz = e1x * e2y - e1y * e2x;

    float nrm = sqrtf(nx * nx + ny * ny + nz * nz);
    float ux = nx / nrm;
    float uy = ny / nrm;
    float uz = nz / nrm;

    float sg = (ux > 0.0f) ? 1.0f : -1.0f;   // NaN compares false -> -1
    ux *= sg; uy *= sg; uz *= sg;

    float cx = (g0x + g1x + g2x) / 3.0f;
    float cy = (g0y + g1y + g2y) / 3.0f;
    float cz = (g0z + g1z + g2z) / 3.0f;

    float pos = (ux * cx + uy * cy + uz * cz) / sqrtf(3.0f);

    bool bad = (ux != ux) || (uy != uy) || (uz != uz);
    g_mask[q] = bad ? 1 : 0;

    // first non-NaN row per batch: warp-reduce then one atomic per warp.
    // Block covers consecutive q within ONE batch (NN % 256 == 0).
    int v = bad ? INT_MAX : n;
    int wmin = __reduce_min_sync(0xffffffffu, v);
    if ((threadIdx.x & 31) == 0 && wmin != INT_MAX)
        atomicMin(&g_first[b], wmin);

    const size_t base = (size_t)b * 3 * NN + n;
    out[OFF_U + base]          = ux;
    out[OFF_U + base + NN]     = uy;
    out[OFF_U + base + 2 * NN] = uz;
    out[OFF_C + base]          = cx;
    out[OFF_C + base + NN]     = cy;
    out[OFF_C + base + 2 * NN] = cz;
    out[OFF_P + (size_t)b * NN + n] = pos;
}

// Rewrite masked rows with the first non-NaN row's values
__global__ void surf_fix_kernel(float* __restrict__ out)
{
    const int idx = blockIdx.x * blockDim.x + threadIdx.x;
    if (idx >= BB * NN) return;
    if (!g_mask[idx]) return;

    const int b = idx / NN;
    const int n = idx % NN;
    int f = g_first[b];
    if (f == INT_MAX) f = 0;   // all-masked: reference argmax(~mask) = 0

    const size_t src = (size_t)b * 3 * NN + f;
    const size_t dst = (size_t)b * 3 * NN + n;

    out[OFF_U + dst]          = out[OFF_U + src];
    out[OFF_U + dst + NN]     = out[OFF_U + src + NN];
    out[OFF_U + dst + 2 * NN] = out[OFF_U + src + 2 * NN];
    out[OFF_C + dst]          = out[OFF_C + src];
    out[OFF_C + dst + NN]     = out[OFF_C + src + NN];
    out[OFF_C + dst + 2 * NN] = out[OFF_C + src + 2 * NN];
    out[OFF_P + (size_t)b * NN + n] = out[OFF_P + (size_t)b * NN + f];
}

extern "C" void kernel_launch(void* const* d_in, const int* in_sizes, int n_in,
                              void* d_out, int out_size)
{
    const float* center  = (const float*)d_in[0];   // [B,3,N]
    const float* context = (const float*)d_in[1];   // [B,3,M]
    float* out = (float*)d_out;

    surf_scan_kernel<<<BB * BPB * SPLIT, TPB>>>(center, context);
    surf_merge_kernel<<<(BB * NN + 255) / 256, 256>>>(context, out);
    surf_fix_kernel<<<(BB * NN + 255) / 256, 256>>>(out);
}